// round 8
// baseline (speedup 1.0000x reference)
#include <cuda_runtime.h>
#include <stdint.h>

// GenerativeUpBlock: pruned generative transpose conv 3x3x3 stride 2.
//   d_in[0] in_feats  f32 [NP,64]   d_in[1] weights f32 [27,64,32]
//   d_in[2] bias      f32 [32]      d_in[3] in_coords [NP,4] (int32 or int64)
//   d_in[4] guide_coords [NG,4]     out: f32 [NG,32]

#define TABLE_SIZE (1 << 21)           // 128^3 dense stride-2 lattice
#define MAXG 400000
#define NOFF 27
#define GB 11                          // blocks per offset in compute kernel

__device__ __align__(16) int g_table[TABLE_SIZE];      // lin -> input row or -1
__device__ int               g_cnt[NOFF];              // per-offset pair counts
__device__ int               g_is64;                   // coord dtype flag
__device__ int2              g_pairs[(size_t)NOFF * MAXG]; // (guide, input) per offset

// ---- packed fp32x2 helpers (Blackwell FFMA2) -------------------------------
__device__ __forceinline__ unsigned long long pk2(float a, float b) {
    unsigned long long r;
    asm("mov.b64 %0, {%1, %2};" : "=l"(r) : "f"(a), "f"(b));
    return r;
}
__device__ __forceinline__ void upk2(unsigned long long v, float& a, float& b) {
    asm("mov.b64 {%0, %1}, %2;" : "=f"(a), "=f"(b) : "l"(v));
}
#define FFMA2(d, a, b, c) \
    asm("fma.rn.f32x2 %0, %1, %2, %3;" : "=l"(d) : "l"(a), "l"(b), "l"(c))

__device__ __forceinline__ void red_add_v4(float* p, float4 v) {
    asm volatile("red.global.add.v4.f32 [%0], {%1, %2, %3, %4};"
                 :: "l"(p), "f"(v.x), "f"(v.y), "f"(v.z), "f"(v.w) : "memory");
}

// Read coord row r as (x,y,z), branching on detected dtype (vector loads).
__device__ __forceinline__ void read_coord(const int* __restrict__ base, int r, int is64,
                                           int& x, int& y, int& z) {
    const int4* p = (const int4*)base;
    if (is64) {
        int4 lo = __ldg(&p[2 * r]);
        int4 hi = __ldg(&p[2 * r + 1]);
        x = lo.z; y = hi.x; z = hi.z;
    } else {
        int4 v = __ldg(&p[r]);
        x = v.y; y = v.z; z = v.w;
    }
}

// ---------------------------------------------------------------------------
// Kernel 1: dtype probe (block 0) + reset table + counters.
// ---------------------------------------------------------------------------
__global__ void k_init(const int* __restrict__ ic) {
    if (blockIdx.x == 0 && threadIdx.x < 32) {
        int nz = (ic[2 * threadIdx.x + 1] != 0);   // odd int32 slots zero iff int64
        unsigned any = __ballot_sync(0xffffffffu, nz);
        if (threadIdx.x == 0) g_is64 = (any == 0u);
    }
    int i = blockIdx.x * blockDim.x + threadIdx.x;
    for (int j = i; j < TABLE_SIZE; j += gridDim.x * blockDim.x)
        g_table[j] = -1;
    if (i < NOFF) g_cnt[i] = 0;
}

// ---------------------------------------------------------------------------
// Kernel 2: scatter input rows into dense table.
// ---------------------------------------------------------------------------
__global__ void k_scatter(const int* __restrict__ ic, int np) {
    int i = blockIdx.x * blockDim.x + threadIdx.x;
    if (i >= np) return;
    int x, y, z;
    read_coord(ic, i, g_is64, x, y, z);
    if ((unsigned)x > 255u || (unsigned)y > 255u || (unsigned)z > 255u) return;
    if ((x | y | z) & 1) return;
    int lin = (x >> 1) | ((y >> 1) << 7) | ((z >> 1) << 14);
    g_table[lin] = i;
}

// ---------------------------------------------------------------------------
// Kernel 3: match (block-aggregated pair emission) + write out rows:
// bias where generated, zero elsewhere (replaces separate outinit kernel).
// ---------------------------------------------------------------------------
__global__ void k_match(const int* __restrict__ gc, const float* __restrict__ bias,
                        float* __restrict__ out, int ng) {
    __shared__ int scnt[NOFF];
    __shared__ int sbase[NOFF];
    __shared__ float4 sb[8];
    const int tid = threadIdx.x;
    if (tid < NOFF) scnt[tid] = 0;
    if (tid < 8) sb[tid] = __ldg(&((const float4*)bias)[tid]);
    __syncthreads();

    const int g = blockIdx.x * blockDim.x + tid;
    int nm = 0;
    int mo[8], mi[8], mslot[8];

    if (g < ng) {
        int qx, qy, qz;
        read_coord(gc, g, g_is64, qx, qy, qz);
        int ox = qx & 1, oy = qy & 1, oz = qz & 1;   // odd axis => d in {-1,1}; even => {0}
        int ndx = ox ? 2 : 1, ndy = oy ? 2 : 1, ndz = oz ? 2 : 1;

        for (int a = 0; a < ndx; a++) {
            int dx = ox ? (a * 2 - 1) : 0;
            int px = qx - dx;
            if ((unsigned)px > 254u) continue;
            for (int b = 0; b < ndy; b++) {
                int dy = oy ? (b * 2 - 1) : 0;
                int py = qy - dy;
                if ((unsigned)py > 254u) continue;
                for (int c = 0; c < ndz; c++) {
                    int dz = oz ? (c * 2 - 1) : 0;
                    int pz = qz - dz;
                    if ((unsigned)pz > 254u) continue;
                    int lin = (px >> 1) | ((py >> 1) << 7) | ((pz >> 1) << 14);
                    int idx = g_table[lin];
                    if (idx >= 0) {
                        mo[nm] = (dx + 1) * 9 + (dy + 1) * 3 + (dz + 1);
                        mi[nm] = idx;
                        nm++;
                    }
                }
            }
        }
        // out row init: bias if generated, zero otherwise
        float4* orow = (float4*)(out + (size_t)g * 32);
        if (nm) {
#pragma unroll
            for (int j = 0; j < 8; j++) orow[j] = sb[j];
        } else {
            float4 z4 = make_float4(0.f, 0.f, 0.f, 0.f);
#pragma unroll
            for (int j = 0; j < 8; j++) orow[j] = z4;
        }
    }

    for (int m = 0; m < nm; m++) mslot[m] = atomicAdd(&scnt[mo[m]], 1);
    __syncthreads();
    if (tid < NOFF && scnt[tid] > 0) sbase[tid] = atomicAdd(&g_cnt[tid], scnt[tid]);
    __syncthreads();
    for (int m = 0; m < nm; m++) {
        int o = mo[m];
        g_pairs[(size_t)o * MAXG + sbase[o] + mslot[m]] = make_int2(g, mi[m]);
    }
}

// ---------------------------------------------------------------------------
// Kernel 4: per-offset gather-GEMV. W[o] packed f32x2 in registers (one output
// column per lane). Feature row staged via double-buffered smem float4
// broadcasts; output reduced with red.global.add.v4.f32 after a smem
// transpose (8 vector REDs per match instead of 32 scalar ones).
// Software-pipelined: next pair record + feature row loaded under compute.
// ---------------------------------------------------------------------------
__global__ void __launch_bounds__(256) k_compute(const float* __restrict__ feats,
                                                 const float* __restrict__ W,
                                                 float* __restrict__ out) {
    const int o     = blockIdx.x % NOFF;
    const int chunk = blockIdx.x / NOFF;
    const int lane  = threadIdx.x & 31;
    const int warp  = threadIdx.x >> 5;

    __shared__ __align__(16) float4 sf[8][2][16];   // feature staging
    __shared__ __align__(16) float  sacc[8][2][32]; // accumulator transpose

    // Packed weights: w2[k] = {W[o][2k][lane], W[o][2k+1][lane]}
    unsigned long long w2[32];
    const float* wp = W + o * (64 * 32);
#pragma unroll
    for (int k = 0; k < 32; k++) {
        float wa = __ldg(&wp[(2 * k) * 32 + lane]);
        float wb = __ldg(&wp[(2 * k + 1) * 32 + lane]);
        w2[k] = pk2(wa, wb);
    }

    const int n   = g_cnt[o];
    const int nw  = GB * 8;
    int p = chunk * 8 + warp;

    int2 pr; float4 v;
    bool valid = (p < n);
    if (valid) {
        pr = g_pairs[(size_t)o * MAXG + p];
        if (lane < 16) v = __ldg(&((const float4*)(feats + (size_t)pr.y * 64))[lane]);
    }

    int buf = 0;
    while (valid) {
        if (lane < 16) sf[warp][buf][lane] = v;
        __syncwarp();

        // prefetch next pair + feature row
        int pn = p + nw;
        bool vn = (pn < n);
        int2 prn; float4 vnxt;
        if (vn) {
            prn = g_pairs[(size_t)o * MAXG + pn];
            if (lane < 16) vnxt = __ldg(&((const float4*)(feats + (size_t)prn.y * 64))[lane]);
        }

        unsigned long long accA = 0ull, accB = 0ull;
#pragma unroll
        for (int k = 0; k < 16; k++) {
            float4 t = sf[warp][buf][k];              // broadcast LDS.128
            unsigned long long lo = pk2(t.x, t.y);
            unsigned long long hi = pk2(t.z, t.w);
            FFMA2(accA, lo, w2[2 * k], accA);
            FFMA2(accB, hi, w2[2 * k + 1], accB);
        }
        float a0, a1, a2, a3;
        upk2(accA, a0, a1);
        upk2(accB, a2, a3);
        sacc[warp][buf][lane] = (a0 + a1) + (a2 + a3);
        __syncwarp();

        if (lane < 8) {
            float4 q = *(const float4*)&sacc[warp][buf][4 * lane];
            red_add_v4(&out[(size_t)pr.x * 32 + 4 * lane], q);
        }

        pr = prn; v = vnxt; p = pn; valid = vn; buf ^= 1;
    }
}

// ---------------------------------------------------------------------------
extern "C" void kernel_launch(void* const* d_in, const int* in_sizes, int n_in,
                              void* d_out, int out_size) {
    const float* feats = (const float*)d_in[0];
    const float* W     = (const float*)d_in[1];
    const float* bias  = (const float*)d_in[2];
    const int*   ic    = (const int*)d_in[3];
    const int*   gc    = (const int*)d_in[4];
    float*       out   = (float*)d_out;

    int np = in_sizes[0] / 64;
    int ng = in_sizes[4] / 4;
    if (ng > MAXG) ng = MAXG;

    k_init<<<1024, 256>>>(ic);
    k_scatter<<<(np + 255) / 256, 256>>>(ic, np);
    k_match<<<(ng + 255) / 256, 256>>>(gc, bias, out, ng);
    k_compute<<<NOFF * GB, 256>>>(feats, W, out);
}

// round 9
// speedup vs baseline: 1.8062x; 1.8062x over previous
#include <cuda_runtime.h>
#include <stdint.h>

// GenerativeUpBlock: pruned generative transpose conv 3x3x3 stride 2.
//   d_in[0] in_feats  f32 [NP,64]   d_in[1] weights f32 [27,64,32]
//   d_in[2] bias      f32 [32]      d_in[3] in_coords [NP,4] (int32 or int64)
//   d_in[4] guide_coords [NG,4]     out: f32 [NG,32]

#define TABLE_SIZE (1 << 21)           // 128^3 dense stride-2 lattice
#define MAXG 400000
#define NOFF 27
#define GB 40                          // blocks per offset in compute kernel
#define CWARPS 4                       // warps per compute block (128 threads)

__device__ __align__(16) int g_table[TABLE_SIZE];      // lin -> input row or -1
__device__ int               g_cnt[NOFF];              // per-offset pair counts
__device__ int               g_is64;                   // coord dtype flag
__device__ int2              g_pairs[(size_t)NOFF * MAXG]; // (guide, input) per offset

// ---- packed fp32x2 helpers (Blackwell FFMA2) -------------------------------
__device__ __forceinline__ unsigned long long pk2(float a, float b) {
    unsigned long long r;
    asm("mov.b64 %0, {%1, %2};" : "=l"(r) : "f"(a), "f"(b));
    return r;
}
__device__ __forceinline__ void upk2(unsigned long long v, float& a, float& b) {
    asm("mov.b64 {%0, %1}, %2;" : "=f"(a), "=f"(b) : "l"(v));
}
#define FFMA2(d, a, b, c) \
    asm("fma.rn.f32x2 %0, %1, %2, %3;" : "=l"(d) : "l"(a), "l"(b), "l"(c))

__device__ __forceinline__ void red_add_v4(float* p, float x, float y, float z, float w) {
    asm volatile("red.global.add.v4.f32 [%0], {%1, %2, %3, %4};"
                 :: "l"(p), "f"(x), "f"(y), "f"(z), "f"(w) : "memory");
}

// Read coord row r as (x,y,z), branching on detected dtype (vector loads).
__device__ __forceinline__ void read_coord(const int* __restrict__ base, int r, int is64,
                                           int& x, int& y, int& z) {
    const int4* p = (const int4*)base;
    if (is64) {
        int4 lo = __ldg(&p[2 * r]);
        int4 hi = __ldg(&p[2 * r + 1]);
        x = lo.z; y = hi.x; z = hi.z;
    } else {
        int4 v = __ldg(&p[r]);
        x = v.y; y = v.z; z = v.w;
    }
}

// ---------------------------------------------------------------------------
// Kernel 1: dtype probe (block 0) + reset table + counters.
// ---------------------------------------------------------------------------
__global__ void k_init(const int* __restrict__ ic) {
    if (blockIdx.x == 0 && threadIdx.x < 32) {
        int nz = (ic[2 * threadIdx.x + 1] != 0);   // odd int32 slots zero iff int64
        unsigned any = __ballot_sync(0xffffffffu, nz);
        if (threadIdx.x == 0) g_is64 = (any == 0u);
    }
    int i = blockIdx.x * blockDim.x + threadIdx.x;
    for (int j = i; j < TABLE_SIZE; j += gridDim.x * blockDim.x)
        g_table[j] = -1;
    if (i < NOFF) g_cnt[i] = 0;
}

// ---------------------------------------------------------------------------
// Kernel 2: scatter input rows into dense table.
// ---------------------------------------------------------------------------
__global__ void k_scatter(const int* __restrict__ ic, int np) {
    int i = blockIdx.x * blockDim.x + threadIdx.x;
    if (i >= np) return;
    int x, y, z;
    read_coord(ic, i, g_is64, x, y, z);
    if ((unsigned)x > 255u || (unsigned)y > 255u || (unsigned)z > 255u) return;
    if ((x | y | z) & 1) return;
    int lin = (x >> 1) | ((y >> 1) << 7) | ((z >> 1) << 14);
    g_table[lin] = i;
}

// ---------------------------------------------------------------------------
// Kernel 3: match (block-aggregated pair emission) + out-row init
// (bias where generated, zero elsewhere).
// ---------------------------------------------------------------------------
__global__ void k_match(const int* __restrict__ gc, const float* __restrict__ bias,
                        float* __restrict__ out, int ng) {
    __shared__ int scnt[NOFF];
    __shared__ int sbase[NOFF];
    __shared__ float4 sb[8];
    const int tid = threadIdx.x;
    if (tid < NOFF) scnt[tid] = 0;
    if (tid < 8) sb[tid] = __ldg(&((const float4*)bias)[tid]);
    __syncthreads();

    const int g = blockIdx.x * blockDim.x + tid;
    int nm = 0;
    int mo[8], mi[8], mslot[8];

    if (g < ng) {
        int qx, qy, qz;
        read_coord(gc, g, g_is64, qx, qy, qz);
        int ox = qx & 1, oy = qy & 1, oz = qz & 1;
        int ndx = ox ? 2 : 1, ndy = oy ? 2 : 1, ndz = oz ? 2 : 1;

        for (int a = 0; a < ndx; a++) {
            int dx = ox ? (a * 2 - 1) : 0;
            int px = qx - dx;
            if ((unsigned)px > 254u) continue;
            for (int b = 0; b < ndy; b++) {
                int dy = oy ? (b * 2 - 1) : 0;
                int py = qy - dy;
                if ((unsigned)py > 254u) continue;
                for (int c = 0; c < ndz; c++) {
                    int dz = oz ? (c * 2 - 1) : 0;
                    int pz = qz - dz;
                    if ((unsigned)pz > 254u) continue;
                    int lin = (px >> 1) | ((py >> 1) << 7) | ((pz >> 1) << 14);
                    int idx = g_table[lin];
                    if (idx >= 0) {
                        mo[nm] = (dx + 1) * 9 + (dy + 1) * 3 + (dz + 1);
                        mi[nm] = idx;
                        nm++;
                    }
                }
            }
        }
        float4* orow = (float4*)(out + (size_t)g * 32);
        if (nm) {
#pragma unroll
            for (int j = 0; j < 8; j++) orow[j] = sb[j];
        } else {
            float4 z4 = make_float4(0.f, 0.f, 0.f, 0.f);
#pragma unroll
            for (int j = 0; j < 8; j++) orow[j] = z4;
        }
    }

    for (int m = 0; m < nm; m++) mslot[m] = atomicAdd(&scnt[mo[m]], 1);
    __syncthreads();
    if (tid < NOFF && scnt[tid] > 0) sbase[tid] = atomicAdd(&g_cnt[tid], scnt[tid]);
    __syncthreads();
    for (int m = 0; m < nm; m++) {
        int o = mo[m];
        g_pairs[(size_t)o * MAXG + sbase[o] + mslot[m]] = make_int2(g, mi[m]);
    }
}

// ---------------------------------------------------------------------------
// Kernel 4: per-offset gather-GEMV, 2 matches per warp-iteration.
// Lanes 0-15 gather feature row A, lanes 16-31 row B (double the rows in
// flight). Weights packed f32x2 in registers (one output column per lane).
// Accumulators transposed via 4 shuffles, reduced with red.global.add.v4.f32
// from 8 lanes. Double-buffered smem staging, one __syncwarp per iteration.
// ---------------------------------------------------------------------------
__global__ void __launch_bounds__(128) k_compute(const float* __restrict__ feats,
                                                 const float* __restrict__ W,
                                                 float* __restrict__ out) {
    const int o     = blockIdx.x % NOFF;
    const int chunk = blockIdx.x / NOFF;
    const int lane  = threadIdx.x & 31;
    const int warp  = threadIdx.x >> 5;
    const int half  = lane >> 4;          // 0: row A, 1: row B
    const int l16   = lane & 15;

    __shared__ __align__(16) float4 sf[CWARPS][2][2][16]; // [warp][buf][row][float4]

    // Packed weights: w2[k] = {W[o][2k][lane], W[o][2k+1][lane]}
    unsigned long long w2[32];
    const float* wp = W + o * (64 * 32);
#pragma unroll
    for (int k = 0; k < 32; k++)
        w2[k] = pk2(__ldg(&wp[(2 * k) * 32 + lane]), __ldg(&wp[(2 * k + 1) * 32 + lane]));

    const int n    = g_cnt[o];
    const int NW   = GB * CWARPS;         // warps per offset
    const int wid  = chunk * CWARPS + warp;
    const int step = 2 * NW;
    const int2* seg = &g_pairs[(size_t)o * MAXG];

    int p = 2 * wid;
    bool hA = (p < n), hB = (p + 1 < n);
    int2 prA, prB;
    if (hA) prA = __ldg(&seg[p]);
    if (hB) prB = __ldg(&seg[p + 1]);
    float4 v;
    {
        int2 pr = half ? prB : prA;
        if (half ? hB : hA)
            v = __ldg(&((const float4*)(feats + (size_t)pr.y * 64))[l16]);
    }

    int buf = 0;
    while (hA) {
        sf[warp][buf][half][l16] = v;
        __syncwarp();

        // ---- prefetch next iteration (pairs + feature rows) ----
        int pn = p + step;
        bool hA2 = (pn < n), hB2 = (pn + 1 < n);
        int2 prA2, prB2;
        if (hA2) prA2 = __ldg(&seg[pn]);
        if (hB2) prB2 = __ldg(&seg[pn + 1]);
        float4 v2;
        {
            int2 pr = half ? prB2 : prA2;
            if (half ? hB2 : hA2)
                v2 = __ldg(&((const float4*)(feats + (size_t)pr.y * 64))[l16]);
        }

        // ---- compute + reduce row A ----
        {
            unsigned long long aA = 0ull, aB = 0ull;
#pragma unroll
            for (int k = 0; k < 16; k++) {
                float4 t = sf[warp][buf][0][k];       // broadcast LDS.128
                unsigned long long lo = pk2(t.x, t.y);
                unsigned long long hi = pk2(t.z, t.w);
                FFMA2(aA, lo, w2[2 * k], aA);
                FFMA2(aB, hi, w2[2 * k + 1], aB);
            }
            float a0, a1, a2, a3;
            upk2(aA, a0, a1); upk2(aB, a2, a3);
            float acc = (a0 + a1) + (a2 + a3);
            int s = (lane * 4) & 31;
            float q0 = __shfl_sync(0xffffffffu, acc, s);
            float q1 = __shfl_sync(0xffffffffu, acc, s + 1);
            float q2 = __shfl_sync(0xffffffffu, acc, s + 2);
            float q3 = __shfl_sync(0xffffffffu, acc, s + 3);
            if (lane < 8)
                red_add_v4(&out[(size_t)prA.x * 32 + 4 * lane], q0, q1, q2, q3);
        }
        // ---- compute + reduce row B ----
        if (hB) {
            unsigned long long aA = 0ull, aB = 0ull;
#pragma unroll
            for (int k = 0; k < 16; k++) {
                float4 t = sf[warp][buf][1][k];
                unsigned long long lo = pk2(t.x, t.y);
                unsigned long long hi = pk2(t.z, t.w);
                FFMA2(aA, lo, w2[2 * k], aA);
                FFMA2(aB, hi, w2[2 * k + 1], aB);
            }
            float a0, a1, a2, a3;
            upk2(aA, a0, a1); upk2(aB, a2, a3);
            float acc = (a0 + a1) + (a2 + a3);
            int s = (lane * 4) & 31;
            float q0 = __shfl_sync(0xffffffffu, acc, s);
            float q1 = __shfl_sync(0xffffffffu, acc, s + 1);
            float q2 = __shfl_sync(0xffffffffu, acc, s + 2);
            float q3 = __shfl_sync(0xffffffffu, acc, s + 3);
            if (lane < 8)
                red_add_v4(&out[(size_t)prB.x * 32 + 4 * lane], q0, q1, q2, q3);
        }

        p = pn; prA = prA2; prB = prB2; hA = hA2; hB = hB2; v = v2; buf ^= 1;
    }
}

// ---------------------------------------------------------------------------
extern "C" void kernel_launch(void* const* d_in, const int* in_sizes, int n_in,
                              void* d_out, int out_size) {
    const float* feats = (const float*)d_in[0];
    const float* W     = (const float*)d_in[1];
    const float* bias  = (const float*)d_in[2];
    const int*   ic    = (const int*)d_in[3];
    const int*   gc    = (const int*)d_in[4];
    float*       out   = (float*)d_out;

    int np = in_sizes[0] / 64;
    int ng = in_sizes[4] / 4;
    if (ng > MAXG) ng = MAXG;

    k_init<<<1024, 256>>>(ic);
    k_scatter<<<(np + 255) / 256, 256>>>(ic, np);
    k_match<<<(ng + 255) / 256, 256>>>(gc, bias, out, ng);
    k_compute<<<NOFF * GB, 128>>>(feats, W, out);
}

// round 10
// speedup vs baseline: 1.8886x; 1.0456x over previous
#include <cuda_runtime.h>
#include <stdint.h>

// GenerativeUpBlock: pruned generative transpose conv 3x3x3 stride 2.
//   d_in[0] in_feats  f32 [NP,64]   d_in[1] weights f32 [27,64,32]
//   d_in[2] bias      f32 [32]      d_in[3] in_coords [NP,4] (int32 or int64)
//   d_in[4] guide_coords [NG,4]     out: f32 [NG,32]

#define TABLE_SIZE (1 << 21)           // 128^3 dense stride-2 lattice
#define MAXG 400000
#define NOFF 27
#define GB 40                          // blocks per offset in compute kernel
#define CWARPS 4                       // warps per compute block (128 threads)
#define RPI 4                          // matches per warp-iteration

__device__ __align__(16) int g_table[TABLE_SIZE];      // lin -> input row or -1
__device__ int               g_cnt[NOFF];              // per-offset pair counts
__device__ int               g_is64;                   // coord dtype flag
__device__ __align__(16) int2 g_pairs[(size_t)NOFF * MAXG + 4]; // +4: int4 overread pad

// ---- packed fp32x2 helpers (Blackwell FFMA2) -------------------------------
__device__ __forceinline__ unsigned long long pk2(float a, float b) {
    unsigned long long r;
    asm("mov.b64 %0, {%1, %2};" : "=l"(r) : "f"(a), "f"(b));
    return r;
}
__device__ __forceinline__ void upk2(unsigned long long v, float& a, float& b) {
    asm("mov.b64 {%0, %1}, %2;" : "=f"(a), "=f"(b) : "l"(v));
}
#define FFMA2(d, a, b, c) \
    asm("fma.rn.f32x2 %0, %1, %2, %3;" : "=l"(d) : "l"(a), "l"(b), "l"(c))

__device__ __forceinline__ void red_add_v4(float* p, float x, float y, float z, float w) {
    asm volatile("red.global.add.v4.f32 [%0], {%1, %2, %3, %4};"
                 :: "l"(p), "f"(x), "f"(y), "f"(z), "f"(w) : "memory");
}

// Read coord row r as (x,y,z), branching on detected dtype (vector loads).
__device__ __forceinline__ void read_coord(const int* __restrict__ base, int r, int is64,
                                           int& x, int& y, int& z) {
    const int4* p = (const int4*)base;
    if (is64) {
        int4 lo = __ldg(&p[2 * r]);
        int4 hi = __ldg(&p[2 * r + 1]);
        x = lo.z; y = hi.x; z = hi.z;
    } else {
        int4 v = __ldg(&p[r]);
        x = v.y; y = v.z; z = v.w;
    }
}

// ---------------------------------------------------------------------------
// Kernel 1: dtype probe (block 0) + reset table + counters.
// ---------------------------------------------------------------------------
__global__ void k_init(const int* __restrict__ ic) {
    if (blockIdx.x == 0 && threadIdx.x < 32) {
        int nz = (ic[2 * threadIdx.x + 1] != 0);   // odd int32 slots zero iff int64
        unsigned any = __ballot_sync(0xffffffffu, nz);
        if (threadIdx.x == 0) g_is64 = (any == 0u);
    }
    int i = blockIdx.x * blockDim.x + threadIdx.x;
    for (int j = i; j < TABLE_SIZE; j += gridDim.x * blockDim.x)
        g_table[j] = -1;
    if (i < NOFF) g_cnt[i] = 0;
}

// ---------------------------------------------------------------------------
// Kernel 2: scatter input rows into dense table.
// ---------------------------------------------------------------------------
__global__ void k_scatter(const int* __restrict__ ic, int np) {
    int i = blockIdx.x * blockDim.x + threadIdx.x;
    if (i >= np) return;
    int x, y, z;
    read_coord(ic, i, g_is64, x, y, z);
    if ((unsigned)x > 255u || (unsigned)y > 255u || (unsigned)z > 255u) return;
    if ((x | y | z) & 1) return;
    int lin = (x >> 1) | ((y >> 1) << 7) | ((z >> 1) << 14);
    g_table[lin] = i;
}

// ---------------------------------------------------------------------------
// Kernel 3: match (block-aggregated pair emission) + out-row init
// (bias where generated, zero elsewhere).
// ---------------------------------------------------------------------------
__global__ void k_match(const int* __restrict__ gc, const float* __restrict__ bias,
                        float* __restrict__ out, int ng) {
    __shared__ int scnt[NOFF];
    __shared__ int sbase[NOFF];
    __shared__ float4 sb[8];
    const int tid = threadIdx.x;
    if (tid < NOFF) scnt[tid] = 0;
    if (tid < 8) sb[tid] = __ldg(&((const float4*)bias)[tid]);
    __syncthreads();

    const int g = blockIdx.x * blockDim.x + tid;
    int nm = 0;
    int mo[8], mi[8], mslot[8];

    if (g < ng) {
        int qx, qy, qz;
        read_coord(gc, g, g_is64, qx, qy, qz);
        int ox = qx & 1, oy = qy & 1, oz = qz & 1;
        int ndx = ox ? 2 : 1, ndy = oy ? 2 : 1, ndz = oz ? 2 : 1;

        for (int a = 0; a < ndx; a++) {
            int dx = ox ? (a * 2 - 1) : 0;
            int px = qx - dx;
            if ((unsigned)px > 254u) continue;
            for (int b = 0; b < ndy; b++) {
                int dy = oy ? (b * 2 - 1) : 0;
                int py = qy - dy;
                if ((unsigned)py > 254u) continue;
                for (int c = 0; c < ndz; c++) {
                    int dz = oz ? (c * 2 - 1) : 0;
                    int pz = qz - dz;
                    if ((unsigned)pz > 254u) continue;
                    int lin = (px >> 1) | ((py >> 1) << 7) | ((pz >> 1) << 14);
                    int idx = g_table[lin];
                    if (idx >= 0) {
                        mo[nm] = (dx + 1) * 9 + (dy + 1) * 3 + (dz + 1);
                        mi[nm] = idx;
                        nm++;
                    }
                }
            }
        }
        float4* orow = (float4*)(out + (size_t)g * 32);
        if (nm) {
#pragma unroll
            for (int j = 0; j < 8; j++) orow[j] = sb[j];
        } else {
            float4 z4 = make_float4(0.f, 0.f, 0.f, 0.f);
#pragma unroll
            for (int j = 0; j < 8; j++) orow[j] = z4;
        }
    }

    for (int m = 0; m < nm; m++) mslot[m] = atomicAdd(&scnt[mo[m]], 1);
    __syncthreads();
    if (tid < NOFF && scnt[tid] > 0) sbase[tid] = atomicAdd(&g_cnt[tid], scnt[tid]);
    __syncthreads();
    for (int m = 0; m < nm; m++) {
        int o = mo[m];
        g_pairs[(size_t)o * MAXG + sbase[o] + mslot[m]] = make_int2(g, mi[m]);
    }
}

// ---------------------------------------------------------------------------
// Kernel 4: per-offset gather-GEMV, 4 matches per warp-iteration.
// Lane halves each gather 2 feature rows (2 LDG.128/lane) -> 4 rows in flight.
// Staged rows read back as ull (LDS.64 broadcast) feeding fma.rn.f32x2
// directly (no pack MOVs). Weights packed f32x2 in registers. Accumulators
// transposed via shuffles, reduced with red.global.add.v4.f32 from 8 lanes.
// Double-buffered staging, depth-1 software pipeline, one syncwarp/iter.
// ---------------------------------------------------------------------------
__global__ void __launch_bounds__(128, 4) k_compute(const float* __restrict__ feats,
                                                    const float* __restrict__ W,
                                                    float* __restrict__ out) {
    const int o     = blockIdx.x % NOFF;
    const int chunk = blockIdx.x / NOFF;
    const int lane  = threadIdx.x & 31;
    const int warp  = threadIdx.x >> 5;
    const int half  = lane >> 4;          // row pair selector
    const int l16   = lane & 15;

    __shared__ __align__(16) float4 sf[CWARPS][2][RPI][16]; // [warp][buf][row][f4]

    // Packed weights: w2[k] = {W[o][2k][lane], W[o][2k+1][lane]}
    unsigned long long w2[32];
    const float* wp = W + o * (64 * 32);
#pragma unroll
    for (int k = 0; k < 32; k++)
        w2[k] = pk2(__ldg(&wp[(2 * k) * 32 + lane]), __ldg(&wp[(2 * k + 1) * 32 + lane]));

    const int n    = g_cnt[o];
    const int NW   = GB * CWARPS;
    const int wid  = chunk * CWARPS + warp;
    const int step = RPI * NW;
    const int2* seg = &g_pairs[(size_t)o * MAXG];

    int p = RPI * wid;
    // pairs p..p+3 (aligned int4 x2; array padded for overread)
    int4 q01, q23;
    if (p < n) {
        q01 = __ldg((const int4*)(seg + p));
        q23 = __ldg((const int4*)(seg + p) + 1);
    }
    // this lane gathers rows (half) and (2+half)
    float4 v0, v1;
    {
        int r0y = half ? q01.w : q01.y;        // pair[half].y   (input row)
        int r1y = half ? q23.w : q23.y;        // pair[2+half].y
        if (p + half < n)
            v0 = __ldg(&((const float4*)(feats + (size_t)r0y * 64))[l16]);
        if (p + 2 + half < n)
            v1 = __ldg(&((const float4*)(feats + (size_t)r1y * 64))[l16]);
    }

    int buf = 0;
    while (p < n) {
        sf[warp][buf][half][l16]     = v0;
        sf[warp][buf][2 + half][l16] = v1;
        __syncwarp();

        int gx[RPI];
        gx[0] = q01.x; gx[1] = q01.z; gx[2] = q23.x; gx[3] = q23.z;
        const int rem = n - p;                 // >=1

        // ---- prefetch next iteration ----
        int pn = p + step;
        int4 n01, n23;
        if (pn < n) {
            n01 = __ldg((const int4*)(seg + pn));
            n23 = __ldg((const int4*)(seg + pn) + 1);
            int r0y = half ? n01.w : n01.y;
            int r1y = half ? n23.w : n23.y;
            if (pn + half < n)
                v0 = __ldg(&((const float4*)(feats + (size_t)r0y * 64))[l16]);
            if (pn + 2 + half < n)
                v1 = __ldg(&((const float4*)(feats + (size_t)r1y * 64))[l16]);
        }

        // ---- compute + reduce rows 0..3 ----
#pragma unroll
        for (int r = 0; r < RPI; r++) {
            if (r < rem) {
                const unsigned long long* srow =
                    (const unsigned long long*)&sf[warp][buf][r][0];
                unsigned long long aA = 0ull, aB = 0ull;
#pragma unroll
                for (int k = 0; k < 16; k++) {
                    unsigned long long t0 = srow[2 * k];       // LDS.64 broadcast
                    unsigned long long t1 = srow[2 * k + 1];
                    FFMA2(aA, t0, w2[2 * k], aA);
                    FFMA2(aB, t1, w2[2 * k + 1], aB);
                }
                float a0, a1, a2, a3;
                upk2(aA, a0, a1); upk2(aB, a2, a3);
                float acc = (a0 + a1) + (a2 + a3);
                int s = (lane * 4) & 31;
                float t0 = __shfl_sync(0xffffffffu, acc, s);
                float t1 = __shfl_sync(0xffffffffu, acc, s + 1);
                float t2 = __shfl_sync(0xffffffffu, acc, s + 2);
                float t3 = __shfl_sync(0xffffffffu, acc, s + 3);
                if (lane < 8)
                    red_add_v4(&out[(size_t)gx[r] * 32 + 4 * lane], t0, t1, t2, t3);
            }
        }

        p = pn; q01 = n01; q23 = n23; buf ^= 1;
    }
}

// ---------------------------------------------------------------------------
extern "C" void kernel_launch(void* const* d_in, const int* in_sizes, int n_in,
                              void* d_out, int out_size) {
    const float* feats = (const float*)d_in[0];
    const float* W     = (const float*)d_in[1];
    const float* bias  = (const float*)d_in[2];
    const int*   ic    = (const int*)d_in[3];
    const int*   gc    = (const int*)d_in[4];
    float*       out   = (float*)d_out;

    int np = in_sizes[0] / 64;
    int ng = in_sizes[4] / 4;
    if (ng > MAXG) ng = MAXG;

    k_init<<<1024, 256>>>(ic);
    k_scatter<<<(np + 255) / 256, 256>>>(ic, np);
    k_match<<<(ng + 255) / 256, 256>>>(gc, bias, out, ng);
    k_compute<<<NOFF * GB, 128>>>(feats, W, out);
}